// round 2
// baseline (speedup 1.0000x reference)
#include <cuda_runtime.h>
#include <math.h>

#define S_LEN   2048
#define NBATCH  64
#define DIN     512
#define HID     512
#define KTOT    1024          // DIN + HID (fused [x;h] GEMM)
#define NBLK    128
#define NTHR    256
#define HPB     4             // hidden units per block
#define NROWS   16            // 4 gates * HPB
#define KC      128           // K chunk streamed through smem
#define NCHUNK  (KTOT / KC)   // 8

// smem layout (floats):
//   Ws    [KTOT][NROWS]      = 16384   (64 KB)  persistent fused weights, k-major
//   in_s  [KC][NBATCH]       =  8192   (32 KB)  streamed [x;h] chunk, k-major
//   part  [4][NROWS][NBATCH] =  4096   (16 KB)  k-split partial gate sums
//   bias  [NROWS]            (padded to 32)
#define OFF_WS    0
#define OFF_IN    16384
#define OFF_PART  (16384 + 8192)
#define OFF_BIAS  (16384 + 8192 + 4096)
#define SMEM_FLOATS (OFF_BIAS + 32)
#define SMEM_BYTES  (SMEM_FLOATS * 4)

__device__ unsigned int g_bar;

__global__ void reset_bar_kernel() { g_bar = 0u; }

__global__ void __launch_bounds__(NTHR, 1)
lstm_persistent_kernel(const float* __restrict__ x,
                       const float* __restrict__ Wih,
                       const float* __restrict__ Whh,
                       const float* __restrict__ bih,
                       const float* __restrict__ bhh,
                       float* __restrict__ out)
{
    extern __shared__ float sm[];
    float* Ws   = sm + OFF_WS;
    float* in_s = sm + OFF_IN;
    float* part = sm + OFF_PART;
    float* bias = sm + OFF_BIAS;

    const int t  = threadIdx.x;
    const int bk = blockIdx.x;

    // ---- Load fused weight slice, k-major: Ws[k][r], r = gate*4 + jj ----
    for (int idx = t; idx < NROWS * KTOT; idx += NTHR) {
        int r = idx >> 10;            // idx / KTOT
        int k = idx & (KTOT - 1);
        int R = ((r >> 2) * HID) + bk * HPB + (r & 3);   // global gate row
        float w = (k < DIN) ? Wih[(size_t)R * DIN + k]
                            : Whh[(size_t)R * HID + (k - DIN)];
        Ws[k * NROWS + r] = w;
    }
    if (t < NROWS) {
        int r = t;
        int R = ((r >> 2) * HID) + bk * HPB + (r & 3);
        bias[r] = bih[R] + bhh[R];
    }

    // ---- thread role decode ----
    // GEMM: kq = K-quarter (within chunk), r4 = gate (row-quad), b4 = batch-quad
    const int kq = t >> 6;
    const int r4 = (t >> 4) & 3;
    const int b4 = t & 15;
    // elementwise: eb = batch, ejj = local hidden unit
    const int eb  = t & 63;
    const int ejj = t >> 6;
    // loader: lb = batch row, lkg = k sub-slice within chunk
    const int lb  = t & 63;
    const int lkg = t >> 6;

    float c_reg = 0.0f;   // persistent cell state for (eb, ejj)

    float* h_out = out;
    float* c_out = out + (size_t)S_LEN * NBATCH * HID;

    __syncthreads();

    float4 rld[8];

    for (int s = 0; s < S_LEN; ++s) {
        const float* xrow = x + ((size_t)s * NBATCH + lb) * DIN;
        const float* hrow = (s > 0) ? (h_out + ((size_t)(s - 1) * NBATCH + lb) * HID)
                                    : (const float*)0;

        // prefetch chunk 0 (always x region)
        {
            int k0 = lkg * 32;
            #pragma unroll
            for (int i = 0; i < 8; ++i)
                rld[i] = *(const float4*)(xrow + k0 + i * 4);
        }

        float acc[4][4];
        #pragma unroll
        for (int ri = 0; ri < 4; ++ri)
            #pragma unroll
            for (int bi = 0; bi < 4; ++bi)
                acc[ri][bi] = 0.0f;

        for (int c = 0; c < NCHUNK; ++c) {
            // store prefetched chunk to smem (k-major, batch contiguous)
            {
                int klb = lkg * 32;
                #pragma unroll
                for (int i = 0; i < 8; ++i) {
                    float4 v = rld[i];
                    int kl = klb + i * 4;
                    in_s[(kl + 0) * NBATCH + lb] = v.x;
                    in_s[(kl + 1) * NBATCH + lb] = v.y;
                    in_s[(kl + 2) * NBATCH + lb] = v.z;
                    in_s[(kl + 3) * NBATCH + lb] = v.w;
                }
            }
            __syncthreads();

            // prefetch next chunk (overlaps with compute below)
            if (c + 1 < NCHUNK) {
                int kg = (c + 1) * KC + lkg * 32;   // global k
                if (kg < DIN) {
                    #pragma unroll
                    for (int i = 0; i < 8; ++i)
                        rld[i] = *(const float4*)(xrow + kg + i * 4);
                } else if (s > 0) {
                    #pragma unroll
                    for (int i = 0; i < 8; ++i)
                        rld[i] = *(const float4*)(hrow + (kg - DIN) + i * 4);
                } else {
                    #pragma unroll
                    for (int i = 0; i < 8; ++i)
                        rld[i] = make_float4(0.f, 0.f, 0.f, 0.f);
                }
            }

            // compute this chunk: each thread covers its 32-wide k slice
            const float* WsC = Ws + (c * KC) * NROWS;
            const int klo = kq * 32;
            #pragma unroll
            for (int kl = 0; kl < 32; ++kl) {
                int k = klo + kl;
                float4 iv = *(const float4*)(in_s + k * NBATCH + (b4 << 2));
                float4 wv = *(const float4*)(WsC + k * NROWS + (r4 << 2));
                acc[0][0] = fmaf(wv.x, iv.x, acc[0][0]);
                acc[0][1] = fmaf(wv.x, iv.y, acc[0][1]);
                acc[0][2] = fmaf(wv.x, iv.z, acc[0][2]);
                acc[0][3] = fmaf(wv.x, iv.w, acc[0][3]);
                acc[1][0] = fmaf(wv.y, iv.x, acc[1][0]);
                acc[1][1] = fmaf(wv.y, iv.y, acc[1][1]);
                acc[1][2] = fmaf(wv.y, iv.z, acc[1][2]);
                acc[1][3] = fmaf(wv.y, iv.w, acc[1][3]);
                acc[2][0] = fmaf(wv.z, iv.x, acc[2][0]);
                acc[2][1] = fmaf(wv.z, iv.y, acc[2][1]);
                acc[2][2] = fmaf(wv.z, iv.z, acc[2][2]);
                acc[2][3] = fmaf(wv.z, iv.w, acc[2][3]);
                acc[3][0] = fmaf(wv.w, iv.x, acc[3][0]);
                acc[3][1] = fmaf(wv.w, iv.y, acc[3][1]);
                acc[3][2] = fmaf(wv.w, iv.z, acc[3][2]);
                acc[3][3] = fmaf(wv.w, iv.w, acc[3][3]);
            }
            __syncthreads();
        }

        // ---- write k-split partials: part[kq][row][batch] ----
        #pragma unroll
        for (int ri = 0; ri < 4; ++ri) {
            float4 v = make_float4(acc[ri][0], acc[ri][1], acc[ri][2], acc[ri][3]);
            *(float4*)(part + ((kq * NROWS) + (r4 << 2) + ri) * NBATCH + (b4 << 2)) = v;
        }
        __syncthreads();

        // ---- elementwise LSTM cell: thread (eb, ejj) ----
        {
            float gv[4];
            #pragma unroll
            for (int gt = 0; gt < 4; ++gt) {
                int row = gt * 4 + ejj;
                float v = bias[row];
                #pragma unroll
                for (int q = 0; q < 4; ++q)
                    v += part[(q * NROWS + row) * NBATCH + eb];
                gv[gt] = v;
            }
            float ig = 1.0f / (1.0f + __expf(-gv[0]));
            float fg = 1.0f / (1.0f + __expf(-gv[1]));
            float gg = tanhf(gv[2]);
            float og = 1.0f / (1.0f + __expf(-gv[3]));
            c_reg = fg * c_reg + ig * gg;
            float hv = og * tanhf(c_reg);

            size_t o = ((size_t)s * NBATCH + eb) * HID + bk * HPB + ejj;
            h_out[o] = hv;
            c_out[o] = c_reg;
        }

        // ---- grid barrier: h[s] visible everywhere before step s+1 ----
        __syncthreads();
        if (t == 0) {
            __threadfence();
            unsigned target = (unsigned)(NBLK) * (unsigned)(s + 1);
            atomicAdd(&g_bar, 1u);
            while (*((volatile unsigned int*)&g_bar) < target) { }
            __threadfence();
        }
        __syncthreads();
    }
}

extern "C" void kernel_launch(void* const* d_in, const int* in_sizes, int n_in,
                              void* d_out, int out_size)
{
    (void)in_sizes; (void)n_in; (void)out_size;
    const float* x   = (const float*)d_in[0];
    const float* Wih = (const float*)d_in[1];
    const float* Whh = (const float*)d_in[2];
    const float* bih = (const float*)d_in[3];
    const float* bhh = (const float*)d_in[4];
    float* out = (float*)d_out;

    static int smem_set = 0;
    if (!smem_set) {
        cudaFuncSetAttribute(lstm_persistent_kernel,
                             cudaFuncAttributeMaxDynamicSharedMemorySize,
                             SMEM_BYTES);
        smem_set = 1;
    }

    reset_bar_kernel<<<1, 1>>>();
    lstm_persistent_kernel<<<NBLK, NTHR, SMEM_BYTES>>>(x, Wih, Whh, bih, bhh, out);
}

// round 7
// speedup vs baseline: 3.4587x; 3.4587x over previous
#include <cuda_runtime.h>
#include <cstdint>
#include <math.h>

#define S_LEN 2048
#define NBATCH 64
#define DIN 512
#define HID 512

// ---------------- helpers ----------------
__device__ __forceinline__ float tf32r(float f) {
    float o; asm("cvt.rna.tf32.f32 %0, %1;" : "=f"(o) : "f"(f)); return o;
}
__device__ __forceinline__ uint32_t f2b(float f) { return __float_as_uint(f); }

__device__ __forceinline__ void mma8(float* c, const uint32_t* a, const uint32_t* b) {
    asm volatile(
        "mma.sync.aligned.m16n8k8.row.col.f32.tf32.tf32.f32 "
        "{%0,%1,%2,%3}, {%4,%5,%6,%7}, {%8,%9}, {%0,%1,%2,%3};"
        : "+f"(c[0]), "+f"(c[1]), "+f"(c[2]), "+f"(c[3])
        : "r"(a[0]), "r"(a[1]), "r"(a[2]), "r"(a[3]), "r"(b[0]), "r"(b[1]));
}
__device__ __forceinline__ float sigm(float x) { return 1.0f / (1.0f + __expf(-x)); }
__device__ __forceinline__ float tanh_f(float x) { return 1.0f - 2.0f / (__expf(2.0f * x) + 1.0f); }

// xp layout: [s][m(64)][r2(32)][b(64)],  r2 = gate*8 + u
__device__ float g_xproj[(size_t)S_LEN * 64 * 32 * 64];
__device__ unsigned int g_bar;
__global__ void reset_bar_kernel() { g_bar = 0u; }

// ================= Phase 1: x_proj = x @ Wih^T + (bih+bhh) =================
// grid (1024, 16); block 256 thr (8 warps: 4 m-warps x 2 n-warps, warp m32 x n64)
// K chunks of 32, double buffered. smem floats:
#define P1_XS0 0
#define P1_XS1 4608          // 128*36
#define P1_WS0 9216
#define P1_WS1 13824
#define P1_BIAS 18432
#define P1_SMEMF 18560
#define P1_SMEM (P1_SMEMF * 4)

__global__ void __launch_bounds__(256, 1)
xproj_kernel(const float* __restrict__ x, const float* __restrict__ Wih,
             const float* __restrict__ bih, const float* __restrict__ bhh)
{
    extern __shared__ float smf[];
    const int tid = threadIdx.x, wid = tid >> 5, lane = tid & 31;
    const int g = lane >> 2, tg = lane & 3;
    const int tt = blockIdx.x, gg = blockIdx.y;
    const int wm = wid & 3, wn = wid >> 2;

    if (tid < 128) smf[P1_BIAS + tid] = bih[gg * 128 + tid] + bhh[gg * 128 + tid];

    const int f4 = tid & 7, row0 = tid >> 3;     // loader role
    float4 rx[4], rw[4];

    // prologue: chunk 0
    #pragma unroll
    for (int p = 0; p < 4; ++p) {
        int r = row0 + p * 32;
        rx[p] = *(const float4*)(x + ((size_t)(tt * 128 + r)) * 512 + f4 * 4);
        rw[p] = *(const float4*)(Wih + ((size_t)(gg * 128 + r)) * 512 + f4 * 4);
    }
    #pragma unroll
    for (int p = 0; p < 4; ++p) {
        int r = row0 + p * 32;
        float4 v = rx[p];
        v.x = tf32r(v.x); v.y = tf32r(v.y); v.z = tf32r(v.z); v.w = tf32r(v.w);
        *(float4*)(smf + P1_XS0 + r * 36 + f4 * 4) = v;
        v = rw[p];
        v.x = tf32r(v.x); v.y = tf32r(v.y); v.z = tf32r(v.z); v.w = tf32r(v.w);
        *(float4*)(smf + P1_WS0 + r * 36 + f4 * 4) = v;
    }
    __syncthreads();

    float acc[2][8][4];
    #pragma unroll
    for (int mt = 0; mt < 2; ++mt)
        #pragma unroll
        for (int nt = 0; nt < 8; ++nt)
            #pragma unroll
            for (int q = 0; q < 4; ++q) acc[mt][nt][q] = 0.0f;

    for (int c = 0; c < 16; ++c) {
        if (c < 15) {
            int kc = (c + 1) * 32;
            #pragma unroll
            for (int p = 0; p < 4; ++p) {
                int r = row0 + p * 32;
                rx[p] = *(const float4*)(x + ((size_t)(tt * 128 + r)) * 512 + kc + f4 * 4);
                rw[p] = *(const float4*)(Wih + ((size_t)(gg * 128 + r)) * 512 + kc + f4 * 4);
            }
        }
        const float* xb = smf + ((c & 1) ? P1_XS1 : P1_XS0);
        const float* wb = smf + ((c & 1) ? P1_WS1 : P1_WS0);
        #pragma unroll
        for (int ks = 0; ks < 4; ++ks) {
            uint32_t afr[2][4], bfr[8][2];
            #pragma unroll
            for (int mt = 0; mt < 2; ++mt) {
                int mrb = wm * 32 + mt * 16;
                afr[mt][0] = f2b(xb[(mrb + g) * 36 + ks * 8 + tg]);
                afr[mt][1] = f2b(xb[(mrb + g + 8) * 36 + ks * 8 + tg]);
                afr[mt][2] = f2b(xb[(mrb + g) * 36 + ks * 8 + tg + 4]);
                afr[mt][3] = f2b(xb[(mrb + g + 8) * 36 + ks * 8 + tg + 4]);
            }
            #pragma unroll
            for (int nt = 0; nt < 8; ++nt) {
                int nb = wn * 64 + nt * 8;
                bfr[nt][0] = f2b(wb[(nb + g) * 36 + ks * 8 + tg]);
                bfr[nt][1] = f2b(wb[(nb + g) * 36 + ks * 8 + tg + 4]);
            }
            #pragma unroll
            for (int mt = 0; mt < 2; ++mt)
                #pragma unroll
                for (int nt = 0; nt < 8; ++nt)
                    mma8(acc[mt][nt], afr[mt], bfr[nt]);
        }
        if (c < 15) {
            float* xd = smf + (((c + 1) & 1) ? P1_XS1 : P1_XS0);
            float* wd = smf + (((c + 1) & 1) ? P1_WS1 : P1_WS0);
            #pragma unroll
            for (int p = 0; p < 4; ++p) {
                int r = row0 + p * 32;
                float4 v = rx[p];
                v.x = tf32r(v.x); v.y = tf32r(v.y); v.z = tf32r(v.z); v.w = tf32r(v.w);
                *(float4*)(xd + r * 36 + f4 * 4) = v;
                v = rw[p];
                v.x = tf32r(v.x); v.y = tf32r(v.y); v.z = tf32r(v.z); v.w = tf32r(v.w);
                *(float4*)(wd + r * 36 + f4 * 4) = v;
            }
        }
        __syncthreads();
    }

    // stage [lt 128][lg 128], pad 133 (conflict-free)
    float* stg = smf;
    #pragma unroll
    for (int mt = 0; mt < 2; ++mt) {
        int ltb = wm * 32 + mt * 16;
        #pragma unroll
        for (int nt = 0; nt < 8; ++nt) {
            int lg = wn * 64 + nt * 8 + tg * 2;
            stg[(ltb + g) * 133 + lg]     = acc[mt][nt][0];
            stg[(ltb + g) * 133 + lg + 1] = acc[mt][nt][1];
            stg[(ltb + g + 8) * 133 + lg]     = acc[mt][nt][2];
            stg[(ltb + g + 8) * 133 + lg + 1] = acc[mt][nt][3];
        }
    }
    __syncthreads();

    // copy-out: chunks (s_l 0..1, m_l 0..15), each contiguous [u8][b64]
    const int gate = gg >> 2;
    const int m0 = (gg & 3) * 16;
    const int s0 = tt * 2;
    #pragma unroll
    for (int rep = 0; rep < 16; ++rep) {
        int lin = rep * 256 + tid;
        int chunk = lin >> 7, within = lin & 127;
        int u = within >> 4, b4 = (within & 15) * 4;
        int s_l = chunk >> 4, m_l = chunk & 15;
        int lg = m_l * 8 + u;
        float bsv = smf[P1_BIAS + lg];
        float4 v;
        v.x = stg[(s_l * 64 + b4 + 0) * 133 + lg] + bsv;
        v.y = stg[(s_l * 64 + b4 + 1) * 133 + lg] + bsv;
        v.z = stg[(s_l * 64 + b4 + 2) * 133 + lg] + bsv;
        v.w = stg[(s_l * 64 + b4 + 3) * 133 + lg] + bsv;
        size_t ob = (((size_t)(s0 + s_l) * 64 + (m0 + m_l)) * 32 + gate * 8 + u) * 64 + b4;
        *(float4*)(g_xproj + ob) = v;
    }
}

// ================= Phase 2: persistent recurrence =================
// 64 blocks x 512 thr (16 warps: mh = wid>>3, kg = wid&7).
// Block m owns units m*8..m*8+7; local row r2 = gate*8 + u (32 rows).
// smem floats:
#define P2_HK 0                         // hk[kg(8)][b(64)][68]
#define P2_RED 34816                    // red[16][16][68]
#define P2_XPT 52224                    // xpT[32][68]
#define P2_SMEMF 54400
#define P2_SMEM (P2_SMEMF * 4)
#define P2_NBLK 64

__global__ void __launch_bounds__(512, 1)
lstm_rec_kernel(const float* __restrict__ Whh, float* __restrict__ out)
{
    extern __shared__ float smf[];
    const int tid = threadIdx.x, wid = tid >> 5, lane = tid & 31;
    const int g = lane >> 2, tg = lane & 3;
    const int m = blockIdx.x;
    const int mh = wid >> 3, kg = wid & 7;

    // ---- persistent A fragments (W_hh rows for this warp) ----
    uint32_t afr[8][4];
    {
        int r2a = mh * 16 + g;                               // local row
        int G0 = (r2a >> 3) * 512 + m * 8 + (r2a & 7);
        int r2b = r2a + 8;
        int G1 = (r2b >> 3) * 512 + m * 8 + (r2b & 7);
        const float* W0 = Whh + (size_t)G0 * 512 + kg * 64 + tg;
        const float* W1 = Whh + (size_t)G1 * 512 + kg * 64 + tg;
        #pragma unroll
        for (int ks = 0; ks < 8; ++ks) {
            afr[ks][0] = f2b(tf32r(W0[ks * 8]));
            afr[ks][1] = f2b(tf32r(W1[ks * 8]));
            afr[ks][2] = f2b(tf32r(W0[ks * 8 + 4]));
            afr[ks][3] = f2b(tf32r(W1[ks * 8 + 4]));
        }
    }

    float* h_out = out;
    float* c_out = out + (size_t)S_LEN * NBATCH * HID;
    float c_state = 0.0f;
    __syncthreads();

    for (int s = 0; s < S_LEN; ++s) {
        // xp prefetch -> xpT[r2][b] (pad 68)
        {
            int r2 = tid >> 4, b4 = (tid & 15) * 4;
            float4 v = *(const float4*)(g_xproj + (((size_t)s * 64 + m) * 32 + r2) * 64 + b4);
            *(float4*)(smf + P2_XPT + r2 * 68 + b4) = v;
        }

        if (s > 0) {
            // ---- load h slice: warp (mh,kg) loads b in [mh*32, mh*32+32) of k-slice kg ----
            const float* hbase = h_out + ((size_t)(s - 1) * 64) * 512 + kg * 64;
            int lrow2 = lane >> 4, f4 = lane & 15;
            #pragma unroll
            for (int rr = 0; rr < 16; ++rr) {
                int b = mh * 32 + rr * 2 + lrow2;
                float4 v = *(const float4*)(hbase + (size_t)b * 512 + f4 * 4);
                v.x = tf32r(v.x); v.y = tf32r(v.y); v.z = tf32r(v.z); v.w = tf32r(v.w);
                *(float4*)(smf + P2_HK + (kg * 64 + b) * 68 + f4 * 4) = v;
            }
            asm volatile("bar.sync %0, %1;" :: "r"(kg + 1), "r"(64) : "memory");

            // ---- MMA: D[m16, n64] partial over K=64 ----
            float acc[8][4];
            #pragma unroll
            for (int nt = 0; nt < 8; ++nt)
                #pragma unroll
                for (int q = 0; q < 4; ++q) acc[nt][q] = 0.0f;

            const float* hkb = smf + P2_HK + kg * 64 * 68;
            #pragma unroll
            for (int ks = 0; ks < 8; ++ks) {
                uint32_t bfr[8][2];
                #pragma unroll
                for (int nt = 0; nt < 8; ++nt) {
                    bfr[nt][0] = f2b(hkb[(nt * 8 + g) * 68 + ks * 8 + tg]);
                    bfr[nt][1] = f2b(hkb[(nt * 8 + g) * 68 + ks * 8 + tg + 4]);
                }
                #pragma unroll
                for (int nt = 0; nt < 8; ++nt)
                    mma8(acc[nt], afr[ks], bfr[nt]);
            }
            // ---- store partials ----
            float* rw = smf + P2_RED + wid * 16 * 68;
            #pragma unroll
            for (int nt = 0; nt < 8; ++nt) {
                int col = nt * 8 + tg * 2;
                rw[g * 68 + col]     = acc[nt][0];
                rw[g * 68 + col + 1] = acc[nt][1];
                rw[(g + 8) * 68 + col]     = acc[nt][2];
                rw[(g + 8) * 68 + col + 1] = acc[nt][3];
            }
        }
        __syncthreads();

        // ---- reduce 8 kg partials + xp -> xpT in place ----
        {
            int r = tid >> 4, bq = (tid & 15) * 4;
            int mh2 = r >> 4, rr = r & 15;
            float4 v = *(float4*)(smf + P2_XPT + r * 68 + bq);
            if (s > 0) {
                #pragma unroll
                for (int k2 = 0; k2 < 8; ++k2) {
                    float4 p = *(float4*)(smf + P2_RED + ((mh2 * 8 + k2) * 16 + rr) * 68 + bq);
                    v.x += p.x; v.y += p.y; v.z += p.z; v.w += p.w;
                }
            }
            *(float4*)(smf + P2_XPT + r * 68 + bq) = v;
        }
        __syncthreads();

        // ---- cell: thread (u = tid&7, b = tid>>3) ----
        {
            int u = tid & 7, b = tid >> 3;
            float iv = smf[P2_XPT + (0 * 8 + u) * 68 + b];
            float fv = smf[P2_XPT + (1 * 8 + u) * 68 + b];
            float gv = smf[P2_XPT + (2 * 8 + u) * 68 + b];
            float ov = smf[P2_XPT + (3 * 8 + u) * 68 + b];
            float cv = sigm(fv) * c_state + sigm(iv) * tanh_f(gv);
            c_state = cv;
            float hv = sigm(ov) * tanh_f(cv);
            size_t o = ((size_t)s * 64 + b) * 512 + m * 8 + u;
            h_out[o] = hv;
            c_out[o] = cv;
        }
        __syncthreads();
        if (tid == 0) {
            __threadfence();
            atomicAdd(&g_bar, 1u);
            unsigned tgt = (unsigned)P2_NBLK * (unsigned)(s + 1);
            while (*((volatile unsigned int*)&g_bar) < tgt) { }
            __threadfence();
        }
        __syncthreads();
    }
}

extern "C" void kernel_launch(void* const* d_in, const int* in_sizes, int n_in,
                              void* d_out, int out_size)
{
    (void)in_sizes; (void)n_in; (void)out_size;
    const float* x   = (const float*)d_in[0];
    const float* Wih = (const float*)d_in[1];
    const float* Whh = (const float*)d_in[2];
    const float* bih = (const float*)d_in[3];
    const float* bhh = (const float*)d_in[4];
    float* out = (float*)d_out;

    static int once = 0;
    if (!once) {
        cudaFuncSetAttribute(xproj_kernel, cudaFuncAttributeMaxDynamicSharedMemorySize, P1_SMEM);
        cudaFuncSetAttribute(lstm_rec_kernel, cudaFuncAttributeMaxDynamicSharedMemorySize, P2_SMEM);
        once = 1;
    }
    reset_bar_kernel<<<1, 1>>>();
    xproj_kernel<<<dim3(1024, 16), 256, P1_SMEM>>>(x, Wih, bih, bhh);
    lstm_rec_kernel<<<P2_NBLK, 512, P2_SMEM>>>(Whh, out);
}